// round 1
// baseline (speedup 1.0000x reference)
#include <cuda_runtime.h>
#include <cstdint>

#define B_  4096
#define T_  1024
#define H_  64
#define G_  192   // 3*H

// Scratch for final hidden states: rows 0..4095 = seq1, 4096..8191 = seq2
__device__ float g_hlast[2 * B_ * H_];

// ---- packed f32x2 FMA (FFMA2) ----
__device__ __forceinline__ unsigned long long ffma2(unsigned long long a,
                                                    unsigned long long b,
                                                    unsigned long long c) {
    unsigned long long d;
    asm("fma.rn.f32x2 %0, %1, %2, %3;" : "=l"(d) : "l"(a), "l"(b), "l"(c));
    return d;
}
__device__ __forceinline__ float pair_sum(unsigned long long v) {
    float lo, hi;
    asm("mov.b64 {%0, %1}, %2;" : "=f"(lo), "=f"(hi) : "l"(v));
    return lo + hi;
}

// ---- fast accurate sigmoid/tanh (ex2.approx + rcp.approx: ~2 ulp) ----
__device__ __forceinline__ float ex2f(float x) { float r; asm("ex2.approx.f32 %0, %1;" : "=f"(r) : "f"(x)); return r; }
__device__ __forceinline__ float rcpf(float x) { float r; asm("rcp.approx.f32 %0, %1;" : "=f"(r) : "f"(x)); return r; }
__device__ __forceinline__ float sigm(float x) {
    return rcpf(1.0f + ex2f(-1.4426950408889634f * x));
}
__device__ __forceinline__ float tanh_(float x) {
    // tanh(x) = 2*sigmoid(2x) - 1
    return fmaf(2.0f, sigm(2.0f * x), -1.0f);
}

// ============================================================================
// GRU kernel: 1024 warps, each warp owns 8 rows = 4 batch indices x {x1, x2}.
// W_hh lives in smem as float2 K-pairs: Wp[k2][j] = {W[j][2k2], W[j][2k2+1]}.
// h broadcast per warp via smem; matvec accumulates in packed f32x2.
// ============================================================================
__global__ __launch_bounds__(256, 1)
void gru_kernel(const float* __restrict__ x1, const float* __restrict__ x2,
                const float* __restrict__ Wih, const float* __restrict__ Whh,
                const float* __restrict__ bih, const float* __restrict__ bhh)
{
    extern __shared__ float smem[];
    float2* Wp = reinterpret_cast<float2*>(smem);     // [32][192] float2 = 48 KB
    float*  hb = smem + 2 * 32 * G_;                  // [8 warps][8 rows][64] = 16 KB

    const int tid = threadIdx.x;
    const int w   = tid >> 5;
    const int l   = tid & 31;

    // Stage W_hh into smem as K-pairs
    for (int i = tid; i < 32 * G_; i += 256) {
        int k2 = i / G_, j = i % G_;
        Wp[i] = make_float2(Whh[j * H_ + 2 * k2], Whh[j * H_ + 2 * k2 + 1]);
    }
    // Zero h buffers (h0 = 0)
    for (int i = tid; i < 8 * 8 * H_; i += 256) hb[i] = 0.0f;

    // Per-lane gate-column constants: lane owns j = l + 32*g, g=0..5
    float wi0[6], wi1[6], wi2[6], bi[6], bh[6];
#pragma unroll
    for (int g = 0; g < 6; g++) {
        int j = l + 32 * g;
        wi0[g] = Wih[j * 3 + 0];
        wi1[g] = Wih[j * 3 + 1];
        wi2[g] = Wih[j * 3 + 2];
        bi[g]  = bih[j];
        bh[g]  = bhh[j];
    }

    const int wg = blockIdx.x * 8 + w;   // global warp id, 0..1023
    const int b0 = wg * 4;               // 4 batch indices per warp

    // x fetch: lanes 0..23 each own one (row, component)
    const float* xp = nullptr;
    if (l < 24) {
        int rr = l / 3, c = l % 3;
        int batch = b0 + (rr & 3);
        const float* base = (rr < 4) ? x1 : x2;
        xp = base + (size_t)batch * T_ * 3 + c;
    }

    float hlo[8], hhi[8];
#pragma unroll
    for (int r = 0; r < 8; r++) { hlo[r] = 0.0f; hhi[r] = 0.0f; }

    float* hbw = hb + w * 8 * H_;
    const unsigned long long* hrow = reinterpret_cast<const unsigned long long*>(hbw);

    __syncthreads();

    float preS[8][6];

    for (int t = 0; t < T_; t++) {
        // Issue x load early; consumed only in the epilogue (latency hidden)
        float xv = (l < 24) ? __ldg(xp + t * 3) : 0.0f;

        // Two passes over K (g = 0..2, then 3..5) keep register pressure sane
#pragma unroll
        for (int p = 0; p < 2; p++) {
            const int gb = p * 3;
            unsigned long long acc[8][3];
#pragma unroll
            for (int r = 0; r < 8; r++)
#pragma unroll
                for (int q = 0; q < 3; q++) acc[r][q] = 0ull;

#pragma unroll 8
            for (int k2 = 0; k2 < 32; k2++) {
                unsigned long long w0 = *reinterpret_cast<const unsigned long long*>(&Wp[k2 * G_ + l + 32 * (gb + 0)]);
                unsigned long long w1 = *reinterpret_cast<const unsigned long long*>(&Wp[k2 * G_ + l + 32 * (gb + 1)]);
                unsigned long long w2 = *reinterpret_cast<const unsigned long long*>(&Wp[k2 * G_ + l + 32 * (gb + 2)]);
#pragma unroll
                for (int r = 0; r < 8; r++) {
                    unsigned long long hv = hrow[r * 32 + k2];   // 8B broadcast
                    acc[r][0] = ffma2(hv, w0, acc[r][0]);
                    acc[r][1] = ffma2(hv, w1, acc[r][1]);
                    acc[r][2] = ffma2(hv, w2, acc[r][2]);
                }
            }
#pragma unroll
            for (int r = 0; r < 8; r++)
#pragma unroll
                for (int q = 0; q < 3; q++)
                    preS[r][gb + q] = pair_sum(acc[r][q]);
        }

        __syncwarp();  // all lanes done reading h before anyone overwrites it

#pragma unroll
        for (int r = 0; r < 8; r++) {
            float x0  = __shfl_sync(0xffffffffu, xv, r * 3 + 0);
            float x1v = __shfl_sync(0xffffffffu, xv, r * 3 + 1);
            float x2v = __shfl_sync(0xffffffffu, xv, r * 3 + 2);

            float ax[6], aa[6];
#pragma unroll
            for (int g = 0; g < 6; g++) {
                ax[g] = fmaf(x2v, wi2[g], fmaf(x1v, wi1[g], fmaf(x0, wi0[g], bi[g])));
                aa[g] = preS[r][g] + bh[g];
            }
            // gate order (r, z, n); lane covers j = l (lo) and j = l+32 (hi)
            float rg0 = sigm(aa[0] + ax[0]);
            float rg1 = sigm(aa[1] + ax[1]);
            float zg0 = sigm(aa[2] + ax[2]);
            float zg1 = sigm(aa[3] + ax[3]);
            float ng0 = tanh_(fmaf(rg0, aa[4], ax[4]));  // xn + r*hn (biases split correctly)
            float ng1 = tanh_(fmaf(rg1, aa[5], ax[5]));

            hlo[r] = fmaf(zg0, hlo[r] - ng0, ng0);       // (1-z)n + z h
            hhi[r] = fmaf(zg1, hhi[r] - ng1, ng1);

            hbw[r * H_ + l]      = hlo[r];
            hbw[r * H_ + l + 32] = hhi[r];
        }
        __syncwarp();  // stores visible before next step's broadcasts
    }

    // Final hidden states
#pragma unroll
    for (int r = 0; r < 8; r++) {
        int rowg = (r >> 2) * B_ + b0 + (r & 3);
        g_hlast[rowg * H_ + l]      = hlo[r];
        g_hlast[rowg * H_ + l + 32] = hhi[r];
    }
}

// ============================================================================
// Head: out[b] = sigmoid(W2 @ relu(W1 @ |h1-h2| + b1) + b2)
// One 32-thread block per batch element.
// ============================================================================
__global__ void head_kernel(const float* __restrict__ W1, const float* __restrict__ b1,
                            const float* __restrict__ W2, const float* __restrict__ b2,
                            float* __restrict__ out)
{
    __shared__ float w1s[32 * 65];   // padded: bank-conflict-free column walk
    __shared__ float diffs[64];

    const int b = blockIdx.x;
    const int l = threadIdx.x;

    for (int i = l; i < 32 * 64; i += 32) {
        int m = i >> 6, k = i & 63;
        w1s[m * 65 + k] = W1[i];
    }
    float d0 = fabsf(g_hlast[b * H_ + l]      - g_hlast[(B_ + b) * H_ + l]);
    float d1 = fabsf(g_hlast[b * H_ + 32 + l] - g_hlast[(B_ + b) * H_ + 32 + l]);
    diffs[l]      = d0;
    diffs[32 + l] = d1;
    __syncwarp();

    float acc = b1[l];
#pragma unroll
    for (int k = 0; k < 64; k++) acc = fmaf(w1s[l * 65 + k], diffs[k], acc);
    acc = fmaxf(acc, 0.0f) * W2[l];

#pragma unroll
    for (int o = 16; o > 0; o >>= 1) acc += __shfl_xor_sync(0xffffffffu, acc, o);
    if (l == 0) out[b] = sigm(acc + b2[0]);
}

// ============================================================================
extern "C" void kernel_launch(void* const* d_in, const int* in_sizes, int n_in,
                              void* d_out, int out_size)
{
    (void)in_sizes; (void)n_in; (void)out_size;
    const float* x1  = (const float*)d_in[0];
    const float* x2  = (const float*)d_in[1];
    const float* Wih = (const float*)d_in[2];
    const float* Whh = (const float*)d_in[3];
    const float* bih = (const float*)d_in[4];
    const float* bhh = (const float*)d_in[5];
    const float* W1  = (const float*)d_in[6];
    const float* b1  = (const float*)d_in[7];
    const float* W2  = (const float*)d_in[8];
    const float* b2  = (const float*)d_in[9];
    float* out = (float*)d_out;

    const int dyn_smem = 48 * 1024 + 16 * 1024;  // Wp + h buffers = 64 KB
    cudaFuncSetAttribute(gru_kernel, cudaFuncAttributeMaxDynamicSharedMemorySize, dyn_smem);

    gru_kernel<<<128, 256, dyn_smem>>>(x1, x2, Wih, Whh, bih, bhh);
    head_kernel<<<B_, 32>>>(W1, b1, W2, b2, out);
}

// round 2
// speedup vs baseline: 1.1954x; 1.1954x over previous
#include <cuda_runtime.h>
#include <cstdint>

#define B_   4096
#define T_   1024
#define H_   64
#define G_   192      // 3*H
#define NB   148      // blocks = SMs
#define NW   8        // warps per block
#define RPW  7        // rows per warp (1184*7 = 8288 >= 8192)
#define NROW 8192     // 2*B_

// Final hidden states, row-major: row rho in [0,8192), rho = seq*B_ + batch
__device__ float g_hlast[NROW * H_];

// ---- packed f32x2 FMA ----
__device__ __forceinline__ unsigned long long ffma2(unsigned long long a,
                                                    unsigned long long b,
                                                    unsigned long long c) {
    unsigned long long d;
    asm("fma.rn.f32x2 %0, %1, %2, %3;" : "=l"(d) : "l"(a), "l"(b), "l"(c));
    return d;
}
__device__ __forceinline__ float pair_sum(unsigned long long v) {
    float lo, hi;
    asm("mov.b64 {%0, %1}, %2;" : "=f"(lo), "=f"(hi) : "l"(v));
    return lo + hi;
}

// ---- fast sigmoid/tanh (ex2.approx + rcp.approx, ~2 ulp) ----
__device__ __forceinline__ float ex2f(float x) { float r; asm("ex2.approx.f32 %0, %1;" : "=f"(r) : "f"(x)); return r; }
__device__ __forceinline__ float rcpf(float x) { float r; asm("rcp.approx.f32 %0, %1;" : "=f"(r) : "f"(x)); return r; }
__device__ __forceinline__ float sigm(float x) {
    return rcpf(1.0f + ex2f(-1.4426950408889634f * x));
}
__device__ __forceinline__ float tanh_(float x) {
    return fmaf(2.0f, sigm(2.0f * x), -1.0f);
}

// ============================================================================
// GRU: 148 blocks x 8 warps; each warp owns 7 rows (row = r*1184 + warp_id).
// W_hh in smem as float2 K-pairs: Wp[k2][j] = {W[j][2k2], W[j][2k2+1]}.
// Single pass over all 6 gate columns; h broadcast via LDS.128 (2 K-pairs).
// ============================================================================
__global__ __launch_bounds__(256)
void gru_kernel(const float* __restrict__ x1, const float* __restrict__ x2,
                const float* __restrict__ Wih, const float* __restrict__ Whh,
                const float* __restrict__ bih, const float* __restrict__ bhh)
{
    extern __shared__ float smem[];
    float2* Wp = reinterpret_cast<float2*>(smem);      // [32][192] float2 = 48 KB
    float*  hb = smem + 2 * 32 * G_;                   // [NW][RPW][64] = 14 KB

    const int tid = threadIdx.x;
    const int w   = tid >> 5;
    const int l   = tid & 31;

    // Stage W_hh as K-pairs
    for (int i = tid; i < 32 * G_; i += 256) {
        int k2 = i / G_, j = i % G_;
        Wp[i] = make_float2(Whh[j * H_ + 2 * k2], Whh[j * H_ + 2 * k2 + 1]);
    }
    // h0 = 0
    for (int i = tid; i < NW * RPW * H_; i += 256) hb[i] = 0.0f;

    // Per-lane gate-column constants: lane owns j = l + 32*g, g = 0..5
    float wi0[6], wi1[6], wi2[6], bi[6], bh[6];
#pragma unroll
    for (int g = 0; g < 6; g++) {
        int j = l + 32 * g;
        wi0[g] = Wih[j * 3 + 0];
        wi1[g] = Wih[j * 3 + 1];
        wi2[g] = Wih[j * 3 + 2];
        bi[g]  = bih[j];
        bh[g]  = bhh[j];
    }

    const int wg = blockIdx.x * NW + w;     // global warp id, 0..1183

    // x fetch: lanes 0..20 each own one (row r, component c)
    const float* xp = nullptr;
    if (l < 3 * RPW) {
        int rr = l / 3, c = l % 3;
        int rho = rr * (NB * NW) + wg;
        if (rho >= NROW) rho = NROW - 1;    // dummy rows read row 8191 (harmless)
        const float* base = (rho < B_) ? (x1 + (size_t)rho * T_ * 3)
                                       : (x2 + (size_t)(rho - B_) * T_ * 3);
        xp = base + c;
    }

    float hlo[RPW], hhi[RPW];
#pragma unroll
    for (int r = 0; r < RPW; r++) { hlo[r] = 0.0f; hhi[r] = 0.0f; }

    float* hbw = hb + w * RPW * H_;
    const ulonglong2* hrow4 = reinterpret_cast<const ulonglong2*>(hbw);

    __syncthreads();

    for (int t = 0; t < T_; t++) {
        float xv = (l < 3 * RPW) ? __ldg(xp) : 0.0f;
        xp += 3;

        unsigned long long acc[RPW][6];
#pragma unroll
        for (int r = 0; r < RPW; r++)
#pragma unroll
            for (int g = 0; g < 6; g++) acc[r][g] = 0ull;

        // K loop: k4 covers K-pairs 2k4 and 2k4+1 (4 scalar K per iter)
#pragma unroll 4
        for (int k4 = 0; k4 < 16; k4++) {
            const unsigned long long* pa =
                reinterpret_cast<const unsigned long long*>(Wp + (2 * k4) * G_ + l);
            const unsigned long long* pb = pa + G_;
            unsigned long long wa[6], wb[6];
#pragma unroll
            for (int g = 0; g < 6; g++) { wa[g] = pa[32 * g]; wb[g] = pb[32 * g]; }
#pragma unroll
            for (int r = 0; r < RPW; r++) {
                ulonglong2 hv = hrow4[r * 16 + k4];   // 16B broadcast
#pragma unroll
                for (int g = 0; g < 6; g++) {
                    acc[r][g] = ffma2(hv.x, wa[g], acc[r][g]);
                    acc[r][g] = ffma2(hv.y, wb[g], acc[r][g]);
                }
            }
        }

        __syncwarp();   // all lanes done reading h

#pragma unroll
        for (int r = 0; r < RPW; r++) {
            float x0  = __shfl_sync(0xffffffffu, xv, r * 3 + 0);
            float x1v = __shfl_sync(0xffffffffu, xv, r * 3 + 1);
            float x2v = __shfl_sync(0xffffffffu, xv, r * 3 + 2);

            float ax[6], aa[6];
#pragma unroll
            for (int g = 0; g < 6; g++) {
                ax[g] = fmaf(x2v, wi2[g], fmaf(x1v, wi1[g], fmaf(x0, wi0[g], bi[g])));
                aa[g] = pair_sum(acc[r][g]) + bh[g];
            }
            // gate order (r, z, n); lane covers j = l (lo) and j = l+32 (hi)
            float rg0 = sigm(aa[0] + ax[0]);
            float rg1 = sigm(aa[1] + ax[1]);
            float zg0 = sigm(aa[2] + ax[2]);
            float zg1 = sigm(aa[3] + ax[3]);
            float ng0 = tanh_(fmaf(rg0, aa[4], ax[4]));
            float ng1 = tanh_(fmaf(rg1, aa[5], ax[5]));

            hlo[r] = fmaf(zg0, hlo[r] - ng0, ng0);   // (1-z)*n + z*h
            hhi[r] = fmaf(zg1, hhi[r] - ng1, ng1);

            hbw[r * H_ + l]      = hlo[r];
            hbw[r * H_ + l + 32] = hhi[r];
        }
        __syncwarp();   // stores visible before next step's broadcasts
    }

    // Final hidden states (skip dummy rows)
#pragma unroll
    for (int r = 0; r < RPW; r++) {
        int rho = r * (NB * NW) + wg;
        if (rho < NROW) {
            g_hlast[rho * H_ + l]      = hlo[r];
            g_hlast[rho * H_ + l + 32] = hhi[r];
        }
    }
}

// ============================================================================
// Head: out[b] = sigmoid(W2 @ relu(W1 @ |h1-h2| + b1) + b2)
// ============================================================================
__global__ void head_kernel(const float* __restrict__ W1, const float* __restrict__ b1,
                            const float* __restrict__ W2, const float* __restrict__ b2,
                            float* __restrict__ out)
{
    __shared__ float w1s[32 * 65];
    __shared__ float diffs[64];

    const int b = blockIdx.x;
    const int l = threadIdx.x;

    for (int i = l; i < 32 * 64; i += 32) {
        int m = i >> 6, k = i & 63;
        w1s[m * 65 + k] = W1[i];
    }
    diffs[l]      = fabsf(g_hlast[b * H_ + l]      - g_hlast[(B_ + b) * H_ + l]);
    diffs[32 + l] = fabsf(g_hlast[b * H_ + 32 + l] - g_hlast[(B_ + b) * H_ + 32 + l]);
    __syncwarp();

    float acc = b1[l];
#pragma unroll
    for (int k = 0; k < 64; k++) acc = fmaf(w1s[l * 65 + k], diffs[k], acc);
    acc = fmaxf(acc, 0.0f) * W2[l];

#pragma unroll
    for (int o = 16; o > 0; o >>= 1) acc += __shfl_xor_sync(0xffffffffu, acc, o);
    if (l == 0) out[b] = sigm(acc + b2[0]);
}

// ============================================================================
extern "C" void kernel_launch(void* const* d_in, const int* in_sizes, int n_in,
                              void* d_out, int out_size)
{
    (void)in_sizes; (void)n_in; (void)out_size;
    const float* x1  = (const float*)d_in[0];
    const float* x2  = (const float*)d_in[1];
    const float* Wih = (const float*)d_in[2];
    const float* Whh = (const float*)d_in[3];
    const float* bih = (const float*)d_in[4];
    const float* bhh = (const float*)d_in[5];
    const float* W1  = (const float*)d_in[6];
    const float* b1  = (const float*)d_in[7];
    const float* W2  = (const float*)d_in[8];
    const float* b2  = (const float*)d_in[9];
    float* out = (float*)d_out;

    const int dyn_smem = 2 * 32 * G_ * 4 + NW * RPW * H_ * 4;  // 48K + 14K
    cudaFuncSetAttribute(gru_kernel, cudaFuncAttributeMaxDynamicSharedMemorySize, dyn_smem);

    gru_kernel<<<NB, 32 * NW, dyn_smem>>>(x1, x2, Wih, Whh, bih, bhh);
    head_kernel<<<B_, 32>>>(W1, b1, W2, b2, out);
}